// round 3
// baseline (speedup 1.0000x reference)
#include <cuda_runtime.h>
#include <math.h>

// Problem constants
#define BB 64
#define TT 1024
#define DD 512
#define UU 1024
#define GG 4096           // 4*U
#define MM 65536          // B*T
#define NCTA 128          // persistent recurrent grid

// ---------------- scratch (static __device__, no allocs) ----------------
__device__ float g_xproj[(size_t)MM * GG];        // 1 GiB: x@Wx + bias
__device__ float g_h[2][BB * UU];                 // double-buffered hidden state
__device__ float g_part[4 * BB * GG];             // k-split partial sums (4 MB)
__device__ unsigned g_count;
__device__ unsigned g_release;

// ---------------- packed f32x2 FMA (Blackwell FFMA2, PTX-only) ----------------
__device__ __forceinline__ float2 ffma2(float2 a, float2 b, float2 c) {
    union U { float2 f; unsigned long long u; };
    U x, y, z, r;
    x.f = a; y.f = b; z.f = c;
    asm("fma.rn.f32x2 %0, %1, %2, %3;" : "=l"(r.u) : "l"(x.u), "l"(y.u), "l"(z.u));
    return r.f;
}

__device__ __forceinline__ float sigm(float x) { return 1.0f / (1.0f + expf(-x)); }

// ---------------- grid barrier (monotonic release, L2-coherent) ----------------
__device__ __forceinline__ void gridbar(unsigned s) {
    __syncthreads();
    if (threadIdx.x == 0) {
        __threadfence();
        unsigned prev = atomicAdd(&g_count, 1u);
        if (prev + 1u == (unsigned)NCTA * s) {
            atomicExch(&g_release, s);
        } else {
            volatile unsigned* rel = &g_release;
            while (*rel < s) { }
            __threadfence();
        }
    }
    __syncthreads();
}

// ---------------- init: zero h buffers + barrier state (runs every replay) ----------------
__global__ void k_init() {
    int i = blockIdx.x * blockDim.x + threadIdx.x;
    if (i < 2 * BB * UU) ((float*)g_h)[i] = 0.0f;
    if (i == 0) { g_count = 0u; g_release = 0u; }
}

// ---------------- phase 1: x_proj = inputs(65536x512) @ Wx(512x4096) + bias ----------------
// 128(m) x 64(n) tile, 256 threads, 8x4 microtile, f32x2 paired over m.
__global__ __launch_bounds__(256) void k_xproj(const float* __restrict__ A,
                                               const float* __restrict__ W,
                                               const float* __restrict__ bias) {
    __shared__ float As[16][128];   // k-major
    __shared__ float Ws[16][64];    // n-major
    const int tid = threadIdx.x;
    const int m0 = blockIdx.y * 128;
    const int n0 = blockIdx.x * 64;
    const int ry8 = (tid >> 4) * 8;
    const int cx4 = (tid & 15) * 4;

    float2 acc[4][4];
#pragma unroll
    for (int i = 0; i < 4; i++)
#pragma unroll
        for (int j = 0; j < 4; j++) acc[i][j] = make_float2(0.f, 0.f);

#pragma unroll 1
    for (int kt = 0; kt < DD; kt += 16) {
#pragma unroll
        for (int i = 0; i < 2; i++) {
            int id = tid + i * 256;
            int r = id >> 2;
            int k4 = (id & 3) << 2;
            float4 v = *reinterpret_cast<const float4*>(A + (size_t)(m0 + r) * DD + kt + k4);
            As[k4 + 0][r] = v.x; As[k4 + 1][r] = v.y;
            As[k4 + 2][r] = v.z; As[k4 + 3][r] = v.w;
        }
        {
            int kr = tid >> 4;
            int nc = (tid & 15) << 2;
            *reinterpret_cast<float4*>(&Ws[kr][nc]) =
                *reinterpret_cast<const float4*>(W + (size_t)(kt + kr) * GG + n0 + nc);
        }
        __syncthreads();
#pragma unroll
        for (int kk = 0; kk < 16; kk++) {
            float4 a0 = *reinterpret_cast<const float4*>(&As[kk][ry8]);
            float4 a1 = *reinterpret_cast<const float4*>(&As[kk][ry8 + 4]);
            float4 bv = *reinterpret_cast<const float4*>(&Ws[kk][cx4]);
            float2 A2[4] = {{a0.x, a0.y}, {a0.z, a0.w}, {a1.x, a1.y}, {a1.z, a1.w}};
            float bb4[4] = {bv.x, bv.y, bv.z, bv.w};
#pragma unroll
            for (int mi = 0; mi < 4; mi++)
#pragma unroll
                for (int nj = 0; nj < 4; nj++)
                    acc[mi][nj] = ffma2(A2[mi], make_float2(bb4[nj], bb4[nj]), acc[mi][nj]);
        }
        __syncthreads();
    }

    float b4[4];
#pragma unroll
    for (int j = 0; j < 4; j++) b4[j] = bias[n0 + cx4 + j];
#pragma unroll
    for (int mi = 0; mi < 4; mi++) {
        int r0 = m0 + ry8 + mi * 2;
        float4 o0 = make_float4(acc[mi][0].x + b4[0], acc[mi][1].x + b4[1],
                                acc[mi][2].x + b4[2], acc[mi][3].x + b4[3]);
        float4 o1 = make_float4(acc[mi][0].y + b4[0], acc[mi][1].y + b4[1],
                                acc[mi][2].y + b4[2], acc[mi][3].y + b4[3]);
        *reinterpret_cast<float4*>(g_xproj + (size_t)r0 * GG + n0 + cx4) = o0;
        *reinterpret_cast<float4*>(g_xproj + (size_t)(r0 + 1) * GG + n0 + cx4) = o1;
    }
}

// ---------------- phase 2: persistent recurrence, 128 CTAs x 256 threads ----------------
// Stage A: CTA (kq, ntile) computes partial h[64 x 256k-slice] @ Wh[256 x 128cols]
// Stage B: CTA owns 8 units; reduces 4 partials + xproj, cell update, writes h/out.
__global__ __launch_bounds__(256) void k_recur(const float* __restrict__ W,
                                               float* __restrict__ out) {
    __shared__ float hs[16][64];    // k-major h tile
    __shared__ float Wt[16][128];   // n-major Wh tile
    const int tid = threadIdx.x;
    const int cta = blockIdx.x;
    const int kq = cta >> 5;            // 0..3 (k-split of 1024 into 4x256)
    const int n0 = (cta & 31) * 128;    // column tile
    const int kbase = kq * 256;
    const int ry4 = (tid >> 4) * 4;     // 4 batch rows
    const int cx8 = (tid & 15) * 8;     // 8 columns
    // stage B mapping: 2 cells per thread
    const int idx = tid * 2;
    const int bb = idx >> 3;                 // batch 0..63
    const int u0 = cta * 8 + (idx & 7);      // unit (even), also u0+1
    const float* Wh = W + (size_t)DD * GG;   // recurrent weights = kernel rows [512,1536)

    float c0 = 0.f, c1 = 0.f;

    for (int step = 0; step < TT; ++step) {
        const int p = step & 1;
        const float* hin = g_h[p];

        float2 acc[4][4];
#pragma unroll
        for (int i = 0; i < 4; i++)
#pragma unroll
            for (int j = 0; j < 4; j++) acc[i][j] = make_float2(0.f, 0.f);

#pragma unroll 1
        for (int kt = 0; kt < 256; kt += 16) {
            {
                int b = tid >> 2;
                int k4 = (tid & 3) << 2;
                float4 v = __ldcg(reinterpret_cast<const float4*>(
                    hin + (size_t)b * UU + kbase + kt + k4));
                hs[k4 + 0][b] = v.x; hs[k4 + 1][b] = v.y;
                hs[k4 + 2][b] = v.z; hs[k4 + 3][b] = v.w;
            }
#pragma unroll
            for (int i = 0; i < 2; i++) {
                int id = tid + i * 256;
                int kr = id >> 5;
                int nc = (id & 31) << 2;
                *reinterpret_cast<float4*>(&Wt[kr][nc]) =
                    *reinterpret_cast<const float4*>(
                        Wh + (size_t)(kbase + kt + kr) * GG + n0 + nc);
            }
            __syncthreads();
#pragma unroll
            for (int kk = 0; kk < 16; kk++) {
                float4 av = *reinterpret_cast<const float4*>(&hs[kk][ry4]);
                float4 b0 = *reinterpret_cast<const float4*>(&Wt[kk][cx8]);
                float4 b1 = *reinterpret_cast<const float4*>(&Wt[kk][cx8 + 4]);
                float am[4] = {av.x, av.y, av.z, av.w};
                float2 B2[4] = {{b0.x, b0.y}, {b0.z, b0.w}, {b1.x, b1.y}, {b1.z, b1.w}};
#pragma unroll
                for (int mi = 0; mi < 4; mi++)
#pragma unroll
                    for (int nj = 0; nj < 4; nj++)
                        acc[mi][nj] = ffma2(make_float2(am[mi], am[mi]), B2[nj], acc[mi][nj]);
            }
            __syncthreads();
        }

        // write partials (L2-coherent)
        {
            float* pp = g_part + (size_t)kq * (BB * GG);
#pragma unroll
            for (int mi = 0; mi < 4; mi++)
#pragma unroll
                for (int nj = 0; nj < 4; nj++)
                    __stcg(reinterpret_cast<float2*>(
                               pp + (size_t)(ry4 + mi) * GG + n0 + cx8 + nj * 2),
                           acc[mi][nj]);
        }
        gridbar(2 * step + 1);

        // Stage B: reduce + cell update
        {
            float hv0 = 0.f, hv1 = 0.f;
            const size_t xrow = ((size_t)bb * TT + step) * GG;
#pragma unroll
            for (int e = 0; e < 2; e++) {
                int u = u0 + e;
                float g[4];
#pragma unroll
                for (int gi = 0; gi < 4; gi++) {
                    int col = gi * UU + u;
                    float s = __ldcg(g_part + (size_t)bb * GG + col)
                            + __ldcg(g_part + (size_t)1 * BB * GG + (size_t)bb * GG + col)
                            + __ldcg(g_part + (size_t)2 * BB * GG + (size_t)bb * GG + col)
                            + __ldcg(g_part + (size_t)3 * BB * GG + (size_t)bb * GG + col);
                    s += g_xproj[xrow + col];
                    g[gi] = s;
                }
                float fg = sigm(g[2] + 1.0f);   // forget_bias = 1.0
                float ig = sigm(g[0]);
                float jg = tanhf(g[1]);
                float og = sigm(g[3]);
                if (e == 0) { c0 = c0 * fg + ig * jg; hv0 = tanhf(c0) * og; }
                else        { c1 = c1 * fg + ig * jg; hv1 = tanhf(c1) * og; }
            }
            __stcg(reinterpret_cast<float2*>(g_h[p ^ 1] + (size_t)bb * UU + u0),
                   make_float2(hv0, hv1));
            *reinterpret_cast<float2*>(out + (size_t)bb * (TT * UU) + (size_t)step * UU + u0) =
                make_float2(hv0, hv1);
        }
        gridbar(2 * step + 2);
    }
}

// ---------------- launch ----------------
extern "C" void kernel_launch(void* const* d_in, const int* in_sizes, int n_in,
                              void* d_out, int out_size) {
    (void)in_sizes; (void)n_in; (void)out_size;
    const float* inputs = (const float*)d_in[0];
    const float* kern   = (const float*)d_in[1];
    const float* bias   = (const float*)d_in[2];
    float* out = (float*)d_out;

    k_init<<<512, 256>>>();
    dim3 g1(GG / 64, MM / 128);   // (64, 512)
    k_xproj<<<g1, 256>>>(inputs, kern, bias);
    k_recur<<<NCTA, 256>>>(kern, out);
}